// round 3
// baseline (speedup 1.0000x reference)
#include <cuda_runtime.h>

#define FULLM 0xffffffffu

constexpr int NQ  = 10;
constexpr int DIN = 256;
constexpr int WPB = 8;   // warps (samples) per block

__host__ __device__ constexpr int par(unsigned v) {
    int p = 0;
    while (v) { p ^= (v & 1); v >>= 1; }
    return p;
}

// Swap register bit r with lane bit r (exchange their physical-qubit roles).
// Slots with j_r == lane_r are fixed; the rest exchange pairwise across lanes.
#define SWAPBIT(R) do {                                                        \
    const int lb_ = (lane >> (R)) & 1;                                         \
    _Pragma("unroll")                                                          \
    for (int j_ = 0; j_ < 32; ++j_) {                                          \
        if (((j_ >> (R)) & 1) == 0) {                                          \
            const int j2_ = j_ | (1 << (R));                                   \
            float sdr_ = lb_ ? sr[j_] : sr[j2_];                               \
            float sdi_ = lb_ ? si[j_] : si[j2_];                               \
            float rr_ = __shfl_xor_sync(FULLM, sdr_, 1 << (R));                \
            float ri_ = __shfl_xor_sync(FULLM, sdi_, 1 << (R));                \
            if (lb_) { sr[j_]  = rr_; si[j_]  = ri_; }                         \
            else     { sr[j2_] = rr_; si[j2_] = ri_; }                         \
        }                                                                      \
    }                                                                          \
} while (0)

// In-register RY-type rotation pairing slots (j, j^MASK).
// Side bit b(j) = lp ^ parity(j & PARJ); update:
//   new[j]  = c*a[j]  + sgn*a[j2],  sgn = b ? s : -s  (partner gets -sgn)
template<int MASK, unsigned PARJ>
__device__ __forceinline__ void rot_inreg(float (&sr)[32], float (&si)[32],
                                          float c, float s, int lp)
{
    const float t = lp ? s : -s;
    constexpr int LOW = MASK & (-MASK);
#pragma unroll
    for (int j = 0; j < 32; ++j) {
        if ((j & LOW) == 0) {
            const int j2 = j ^ MASK;
            const float sj = par((unsigned)j & PARJ) ? -t : t;
            float a0r = sr[j],  a0i = si[j];
            float a1r = sr[j2], a1i = si[j2];
            sr[j]  = c * a0r + sj * a1r;  si[j]  = c * a0i + sj * a1i;
            sr[j2] = c * a1r - sj * a0r;  si[j2] = c * a1i - sj * a0i;
        }
    }
}

__global__ void __launch_bounds__(WPB * 32, 2)
vqc_kernel(const float* __restrict__ x, const float* __restrict__ W,
           const float* __restrict__ b, const float* __restrict__ theta,
           float* __restrict__ out, int batch)
{
    __shared__ __align__(16) float Wt[NQ][DIN];   // transposed W
    __shared__ float bsh[NQ];
    __shared__ float thh[NQ];                // 0.5*theta[0][q][0]
    __shared__ float cz1[NQ], sz1[NQ];       // layer-1 RZ half cos/sin
    __shared__ float cy2[NQ], sy2[NQ];       // layer-2 RY half cos/sin

    const int tid = threadIdx.x;

    for (int i = tid; i < DIN * NQ; i += blockDim.x) {
        int d = i / NQ;
        int q = i - d * NQ;
        Wt[q][d] = W[i];
    }
    if (tid < NQ) {
        bsh[tid] = b[tid];
        thh[tid] = 0.5f * theta[tid * 2 + 0];
        float hz1 = 0.5f * theta[tid * 2 + 1];
        cz1[tid] = cosf(hz1); sz1[tid] = sinf(hz1);
        float hy2 = 0.5f * theta[(NQ + tid) * 2 + 0];
        cy2[tid] = cosf(hy2); sy2[tid] = sinf(hy2);
    }
    __syncthreads();

    const int warp = blockIdx.x * WPB + (tid >> 5);
    if (warp >= batch) return;
    const int lane = tid & 31;

    // ---------------- Dense encoder (vectorized) ----------------------------
    float ang[NQ];
    {
        const float4* xr = reinterpret_cast<const float4*>(x + (size_t)warp * DIN);
        float4 xv0 = xr[lane];        // d = 4*lane..4*lane+3
        float4 xv1 = xr[lane + 32];   // d = 128 + 4*lane ...
#pragma unroll
        for (int q = 0; q < NQ; ++q) {
            const float4* wq = reinterpret_cast<const float4*>(&Wt[q][0]);
            float4 w0 = wq[lane], w1 = wq[lane + 32];
            float acc = xv0.x * w0.x + xv0.y * w0.y + xv0.z * w0.z + xv0.w * w0.w
                      + xv1.x * w1.x + xv1.y * w1.y + xv1.z * w1.z + xv1.w * w1.w;
#pragma unroll
            for (int o = 16; o; o >>= 1) acc += __shfl_xor_sync(FULLM, acc, o);
            ang[q] = acc + bsh[q];
        }
    }

    // ---------------- Initial product state (enc RY + L1 RY + L1 RZ) --------
    // Layout: reg bits 0..4 = phys qubits 0..4, lane bits 0..4 = phys 5..9.
    float lfr = 1.f, lfi = 0.f;
#pragma unroll
    for (int qb = 0; qb < 5; ++qb) {
        const int q = 5 + qb;
        float h = 0.5f * ang[q] + thh[q];
        float sn, c;
        __sincosf(h, &sn, &c);
        float cz = cz1[q], sz = sz1[q];
        int bit = (lane >> qb) & 1;
        float amp = bit ? sn : c;
        float ph  = bit ? sz : -sz;
        float vr = amp * cz;
        float vi = amp * ph;
        float nr = lfr * vr - lfi * vi;
        float ni = lfr * vi + lfi * vr;
        lfr = nr; lfi = ni;
    }
    float u0r[5], u0i[5], u1r[5], u1i[5];
#pragma unroll
    for (int q = 0; q < 5; ++q) {
        float h = 0.5f * ang[q] + thh[q];
        float sn, c;
        __sincosf(h, &sn, &c);
        float cz = cz1[q], sz = sz1[q];
        u0r[q] = c * cz;  u0i[q] = -c * sz;
        u1r[q] = sn * cz; u1i[q] = sn * sz;
    }
    float sr[32], si[32];
    sr[0] = lfr; si[0] = lfi;
#pragma unroll
    for (int q = 0; q < 5; ++q) {
        const int n = 1 << q;
#pragma unroll
        for (int j = n - 1; j >= 0; --j) {
            float xr0 = sr[j], xi0 = si[j];
            sr[j + n] = xr0 * u1r[q] - xi0 * u1i[q];
            si[j + n] = xr0 * u1i[q] + xi0 * u1r[q];
            sr[j]     = xr0 * u0r[q] - xi0 * u0i[q];
            si[j]     = xr0 * u0i[q] + xi0 * u0r[q];
        }
    }

    // ---------------- CNOT chain #1 = relabeling (A = L). Layer-2 RY on
    // logical q pairs PHYSICAL bits {q, q+1} ({9} for q=9); side bit
    // b = parity(phys bits 0..q). Progressive reg<->lane bit swaps keep every
    // pair mask fully in-register.

    // q = 0..3 : mask = reg bits {q,q+1}, b = par(j & (2^(q+1)-1))
    rot_inreg<0x03, 0x01>(sr, si, cy2[0], sy2[0], 0);
    rot_inreg<0x06, 0x03>(sr, si, cy2[1], sy2[1], 0);
    rot_inreg<0x0C, 0x07>(sr, si, cy2[2], sy2[2], 0);
    rot_inreg<0x18, 0x0F>(sr, si, cy2[3], sy2[3], 0);

    // swap phys0<->phys5 ; then q=4 pairs {4,5} = reg bits {4,0}
    SWAPBIT(0);
    rot_inreg<0x11, 0x1E>(sr, si, cy2[4], sy2[4], lane & 1);

    // swap phys1<->phys6 ; q=5 pairs {5,6} = reg bits {0,1}
    SWAPBIT(1);
    rot_inreg<0x03, 0x1D>(sr, si, cy2[5], sy2[5], __popc(lane & 0x03) & 1);

    // swap phys2<->phys7 ; q=6 pairs {6,7} = reg bits {1,2}
    SWAPBIT(2);
    rot_inreg<0x06, 0x1B>(sr, si, cy2[6], sy2[6], __popc(lane & 0x07) & 1);

    // swap phys3<->phys8 ; q=7 pairs {7,8} = reg bits {2,3}
    SWAPBIT(3);
    rot_inreg<0x0C, 0x17>(sr, si, cy2[7], sy2[7], __popc(lane & 0x0F) & 1);

    // swap phys4<->phys9 ; q=8 pairs {8,9} = reg bits {3,4}
    SWAPBIT(4);
    {
        const int lp = __popc(lane & 0x1F) & 1;
        rot_inreg<0x18, 0x0F>(sr, si, cy2[8], sy2[8], lp);
        // q=9 pairs {9} = reg bit 4 only
        rot_inreg<0x10, 0x1F>(sr, si, cy2[9], sy2[9], lp);
    }

    // (Layer-2 RZ dropped: diagonal before a permutation + |.|^2.)
    // ---------------- CNOT chain #2 = relabeling (A = L^2) + measurement ----
    // Final layout: lane bits = phys 0..4, reg bits = phys 5..9.
    // n_t = parity(phys & row_t(L^2)), row_t = {t, t-2, t-4, ...}
    const int p0 = lane & 1;
    const int p1 = (lane >> 1) & 1;
    const int p2 = __popc(lane & 0x05) & 1;
    const int pA = __popc(lane & 0x0A) & 1;   // rows {1,3}
    const int pB = __popc(lane & 0x15) & 1;   // rows {0,2,4}
    const int Llow  = p0 + p1 + p2 + pA + pB;             // t = 0..4
    const int LaneH = pA * 0x15 + pB * 0x0A;              // lane part of t = 5..9

    float acc = 0.f;
#pragma unroll
    for (int j = 0; j < 32; ++j) {
        const int Jbits = (j & 1)
                        | (((j >> 1) & 1) << 1)
                        | (par((unsigned)j & 0x05u) << 2)
                        | (par((unsigned)j & 0x0Au) << 3)
                        | (par((unsigned)j & 0x15u) << 4);
        const int pn = Llow + __popc(Jbits ^ LaneH);
        const float w = 1.0f - 0.2f * (float)pn;
        acc += (sr[j] * sr[j] + si[j] * si[j]) * w;
    }
#pragma unroll
    for (int o = 16; o; o >>= 1) acc += __shfl_xor_sync(FULLM, acc, o);
    if (lane == 0) out[warp] = acc;
}

extern "C" void kernel_launch(void* const* d_in, const int* in_sizes, int n_in,
                              void* d_out, int out_size)
{
    const float* x  = nullptr;
    const float* W  = nullptr;
    const float* b  = nullptr;
    const float* th = nullptr;
    for (int i = 0; i < n_in; ++i) {
        int sz = in_sizes[i];
        if      (sz == 4096 * 256) x  = (const float*)d_in[i];
        else if (sz == 256 * 10)   W  = (const float*)d_in[i];
        else if (sz == 10)         b  = (const float*)d_in[i];
        else if (sz == 2 * 10 * 2) th = (const float*)d_in[i];
    }
    if (!x)  x  = (const float*)d_in[0];
    if (!W)  W  = (const float*)d_in[1];
    if (!b)  b  = (const float*)d_in[2];
    if (!th) th = (const float*)d_in[3];

    int batch = out_size;
    int blocks = (batch + WPB - 1) / WPB;
    vqc_kernel<<<blocks, WPB * 32>>>(x, W, b, th, (float*)d_out, batch);
}

// round 4
// speedup vs baseline: 1.7826x; 1.7826x over previous
#include <cuda_runtime.h>

#define FULLM 0xffffffffu

constexpr int NQ  = 10;
constexpr int DIN = 256;
constexpr int WPB = 8;     // warps (samples) per block
constexpr int TSTRIDE = 36; // transpose row stride (floats): 144B, 16B-aligned, conflict-free reads

__host__ __device__ constexpr int par(unsigned v) {
    int p = 0;
    while (v) { p ^= (v & 1); v >>= 1; }
    return p;
}

// In-register RY-type rotation pairing slots (j, j^MASK).
// Side bit b(j) = lp ^ parity(j & PARJ):
//   new[j]  = c*a[j]  + sgn*a[j2],  sgn = b ? s : -s  (partner gets -sgn)
// (Convention validated in rounds 2/3: rel_err ~9e-7.)
template<int MASK, unsigned PARJ>
__device__ __forceinline__ void rot_inreg(float (&sr)[32], float (&si)[32],
                                          float c, float s, int lp)
{
    const float t = lp ? s : -s;
    constexpr int LOW = MASK & (-MASK);
#pragma unroll
    for (int j = 0; j < 32; ++j) {
        if ((j & LOW) == 0) {
            const int j2 = j ^ MASK;
            const float sj = par((unsigned)j & PARJ) ? -t : t;
            float a0r = sr[j],  a0i = si[j];
            float a1r = sr[j2], a1i = si[j2];
            sr[j]  = c * a0r + sj * a1r;  si[j]  = c * a0i + sj * a1i;
            sr[j2] = c * a1r - sj * a0r;  si[j2] = c * a1i - sj * a0i;
        }
    }
}

__global__ void __launch_bounds__(WPB * 32, 2)
vqc_kernel(const float* __restrict__ x, const float* __restrict__ W,
           const float* __restrict__ b, const float* __restrict__ theta,
           float* __restrict__ out, int batch)
{
    __shared__ __align__(16) float Wt[NQ][DIN];          // transposed W
    __shared__ __align__(16) float tb[WPB][32 * TSTRIDE]; // per-warp transpose buffer
    __shared__ float bsh[NQ];
    __shared__ float thh[NQ];                // 0.5*theta[0][q][0]
    __shared__ float cz1[NQ], sz1[NQ];       // layer-1 RZ half cos/sin
    __shared__ float cy2[NQ], sy2[NQ];       // layer-2 RY half cos/sin

    const int tid = threadIdx.x;

    for (int i = tid; i < DIN * NQ; i += blockDim.x) {
        int d = i / NQ;
        int q = i - d * NQ;
        Wt[q][d] = W[i];
    }
    if (tid < NQ) {
        bsh[tid] = b[tid];
        thh[tid] = 0.5f * theta[tid * 2 + 0];
        float hz1 = 0.5f * theta[tid * 2 + 1];
        cz1[tid] = cosf(hz1); sz1[tid] = sinf(hz1);
        float hy2 = 0.5f * theta[(NQ + tid) * 2 + 0];
        cy2[tid] = cosf(hy2); sy2[tid] = sinf(hy2);
    }
    __syncthreads();

    const int warp = blockIdx.x * WPB + (tid >> 5);
    if (warp >= batch) return;
    const int lane = tid & 31;
    float* buf = tb[tid >> 5];

    // ---------------- Dense encoder (vectorized) ----------------------------
    float ang[NQ];
    {
        const float4* xr = reinterpret_cast<const float4*>(x + (size_t)warp * DIN);
        float4 xv0 = xr[lane];
        float4 xv1 = xr[lane + 32];
#pragma unroll
        for (int q = 0; q < NQ; ++q) {
            const float4* wq = reinterpret_cast<const float4*>(&Wt[q][0]);
            float4 w0 = wq[lane], w1 = wq[lane + 32];
            float acc = xv0.x * w0.x + xv0.y * w0.y + xv0.z * w0.z + xv0.w * w0.w
                      + xv1.x * w1.x + xv1.y * w1.y + xv1.z * w1.z + xv1.w * w1.w;
#pragma unroll
            for (int o = 16; o; o >>= 1) acc += __shfl_xor_sync(FULLM, acc, o);
            ang[q] = acc + bsh[q];
        }
    }

    // ---------------- Initial product state (enc RY + L1 RY + L1 RZ) --------
    // Layout: reg bits 0..4 = phys qubits 0..4, lane bits 0..4 = phys 5..9.
    float lfr = 1.f, lfi = 0.f;
#pragma unroll
    for (int qb = 0; qb < 5; ++qb) {
        const int q = 5 + qb;
        float h = 0.5f * ang[q] + thh[q];
        float sn, c;
        __sincosf(h, &sn, &c);
        float cz = cz1[q], sz = sz1[q];
        int bit = (lane >> qb) & 1;
        float amp = bit ? sn : c;
        float ph  = bit ? sz : -sz;
        float vr = amp * cz;
        float vi = amp * ph;
        float nr = lfr * vr - lfi * vi;
        float ni = lfr * vi + lfi * vr;
        lfr = nr; lfi = ni;
    }
    float u0r[5], u0i[5], u1r[5], u1i[5];
#pragma unroll
    for (int q = 0; q < 5; ++q) {
        float h = 0.5f * ang[q] + thh[q];
        float sn, c;
        __sincosf(h, &sn, &c);
        float cz = cz1[q], sz = sz1[q];
        u0r[q] = c * cz;  u0i[q] = -c * sz;
        u1r[q] = sn * cz; u1i[q] = sn * sz;
    }
    float sr[32], si[32];
    sr[0] = lfr; si[0] = lfi;
#pragma unroll
    for (int q = 0; q < 5; ++q) {
        const int n = 1 << q;
#pragma unroll
        for (int j = n - 1; j >= 0; --j) {
            float xr0 = sr[j], xi0 = si[j];
            sr[j + n] = xr0 * u1r[q] - xi0 * u1i[q];
            si[j + n] = xr0 * u1i[q] + xi0 * u1r[q];
            sr[j]     = xr0 * u0r[q] - xi0 * u0i[q];
            si[j]     = xr0 * u0i[q] + xi0 * u0r[q];
        }
    }

    // ---------------- CNOT chain #1 = relabeling (A = L). Layer-2 RY on
    // logical q pairs PHYSICAL bits {q, q+1} ({9} for q=9); side bit
    // b = parity(phys bits 0..q). Rotations commute -> free ordering.

    // q = 0..3 : reg-only pairs
    rot_inreg<0x03, 0x01>(sr, si, cy2[0], sy2[0], 0);
    rot_inreg<0x06, 0x03>(sr, si, cy2[1], sy2[1], 0);
    rot_inreg<0x0C, 0x07>(sr, si, cy2[2], sy2[2], 0);
    rot_inreg<0x18, 0x0F>(sr, si, cy2[3], sy2[3], 0);

    // q = 4 : pairs phys{4,5} = reg bit 4 & lane bit 0 (validated R2 code)
    {
        const float c = cy2[4], s = sy2[4];
#pragma unroll
        for (int j = 0; j < 16; ++j) {
            const int j2 = j | 16;
            float o0r = __shfl_xor_sync(FULLM, sr[j2], 1);
            float o0i = __shfl_xor_sync(FULLM, si[j2], 1);
            float o1r = __shfl_xor_sync(FULLM, sr[j],  1);
            float o1i = __shfl_xor_sync(FULLM, si[j],  1);
            const float sj  = par((unsigned)j) ? s : -s;
            const float sj2 = -sj;
            sr[j]  = c * sr[j]  + sj  * o0r;  si[j]  = c * si[j]  + sj  * o0i;
            sr[j2] = c * sr[j2] + sj2 * o1r;  si[j2] = c * si[j2] + sj2 * o1i;
        }
    }

    // ---------------- Transpose reg bits <-> lane bits through shared memory
    // New layout: reg bit m = phys 5+m, lane bit m = phys m.
    // Write lane-major (STS.128 over j), read j-major (conflict-free LDS).
    {
#pragma unroll
        for (int k = 0; k < 8; ++k) {
            *reinterpret_cast<float4*>(&buf[lane * TSTRIDE + 4 * k]) =
                make_float4(sr[4 * k], sr[4 * k + 1], sr[4 * k + 2], sr[4 * k + 3]);
        }
        __syncwarp();
#pragma unroll
        for (int j = 0; j < 32; ++j) sr[j] = buf[j * TSTRIDE + lane];
        __syncwarp();
#pragma unroll
        for (int k = 0; k < 8; ++k) {
            *reinterpret_cast<float4*>(&buf[lane * TSTRIDE + 4 * k]) =
                make_float4(si[4 * k], si[4 * k + 1], si[4 * k + 2], si[4 * k + 3]);
        }
        __syncwarp();
#pragma unroll
        for (int j = 0; j < 32; ++j) si[j] = buf[j * TSTRIDE + lane];
    }

    // q = 5..9 : now reg-only. b = par(lane&31) ^ par(j & ((1<<(q-4))-1))
    {
        const int lp = __popc(lane & 0x1F) & 1;
        rot_inreg<0x03, 0x01>(sr, si, cy2[5], sy2[5], lp);
        rot_inreg<0x06, 0x03>(sr, si, cy2[6], sy2[6], lp);
        rot_inreg<0x0C, 0x07>(sr, si, cy2[7], sy2[7], lp);
        rot_inreg<0x18, 0x0F>(sr, si, cy2[8], sy2[8], lp);
        rot_inreg<0x10, 0x1F>(sr, si, cy2[9], sy2[9], lp);
    }

    // (Layer-2 RZ dropped: diagonal before a permutation + |.|^2.)
    // ---------------- CNOT chain #2 = relabeling (A = L^2) + measurement ----
    // Layout: lane bits = phys 0..4, reg bits = phys 5..9 (same as R3 final).
    const int p0 = lane & 1;
    const int p1 = (lane >> 1) & 1;
    const int p2 = __popc(lane & 0x05) & 1;
    const int pA = __popc(lane & 0x0A) & 1;   // rows {1,3}
    const int pB = __popc(lane & 0x15) & 1;   // rows {0,2,4}
    const int Llow  = p0 + p1 + p2 + pA + pB;             // t = 0..4
    const int LaneH = pA * 0x15 + pB * 0x0A;              // lane part of t = 5..9

    float acc = 0.f;
#pragma unroll
    for (int j = 0; j < 32; ++j) {
        const int Jbits = (j & 1)
                        | (((j >> 1) & 1) << 1)
                        | (par((unsigned)j & 0x05u) << 2)
                        | (par((unsigned)j & 0x0Au) << 3)
                        | (par((unsigned)j & 0x15u) << 4);
        const int pn = Llow + __popc(Jbits ^ LaneH);
        const float w = 1.0f - 0.2f * (float)pn;
        acc += (sr[j] * sr[j] + si[j] * si[j]) * w;
    }
#pragma unroll
    for (int o = 16; o; o >>= 1) acc += __shfl_xor_sync(FULLM, acc, o);
    if (lane == 0) out[warp] = acc;
}

extern "C" void kernel_launch(void* const* d_in, const int* in_sizes, int n_in,
                              void* d_out, int out_size)
{
    const float* x  = nullptr;
    const float* W  = nullptr;
    const float* b  = nullptr;
    const float* th = nullptr;
    for (int i = 0; i < n_in; ++i) {
        int sz = in_sizes[i];
        if      (sz == 4096 * 256) x  = (const float*)d_in[i];
        else if (sz == 256 * 10)   W  = (const float*)d_in[i];
        else if (sz == 10)         b  = (const float*)d_in[i];
        else if (sz == 2 * 10 * 2) th = (const float*)d_in[i];
    }
    if (!x)  x  = (const float*)d_in[0];
    if (!W)  W  = (const float*)d_in[1];
    if (!b)  b  = (const float*)d_in[2];
    if (!th) th = (const float*)d_in[3];

    int batch = out_size;
    int blocks = (batch + WPB - 1) / WPB;
    vqc_kernel<<<blocks, WPB * 32>>>(x, W, b, th, (float*)d_out, batch);
}

// round 5
// speedup vs baseline: 2.0417x; 1.1454x over previous
#include <cuda_runtime.h>

#define FULLM 0xffffffffu

typedef unsigned long long ull;

constexpr int NQ  = 10;
constexpr int DIN = 256;
constexpr int WPB = 4;     // warps (samples) per block

__host__ __device__ constexpr int par(unsigned v) {
    int p = 0;
    while (v) { p ^= (v & 1); v >>= 1; }
    return p;
}

// ---- packed f32x2 helpers (sm_103a FFMA2 path) -----------------------------
__device__ __forceinline__ ull pk2(float lo, float hi) {
    ull r; asm("mov.b64 %0, {%1, %2};" : "=l"(r) : "f"(lo), "f"(hi)); return r;
}
__device__ __forceinline__ void upk2(float& lo, float& hi, ull v) {
    asm("mov.b64 {%0, %1}, %2;" : "=f"(lo), "=f"(hi) : "l"(v));
}
__device__ __forceinline__ ull fma2(ull a, ull b, ull c) {
    ull d; asm("fma.rn.f32x2 %0, %1, %2, %3;" : "=l"(d) : "l"(a), "l"(b), "l"(c)); return d;
}
__device__ __forceinline__ ull mul2(ull a, ull b) {
    ull d; asm("mul.rn.f32x2 %0, %1, %2;" : "=l"(d) : "l"(a), "l"(b)); return d;
}
__device__ __forceinline__ ull add2(ull a, ull b) {
    ull d; asm("add.rn.f32x2 %0, %1, %2;" : "=l"(d) : "l"(a), "l"(b)); return d;
}

// Packed RY-type rotation pairing slots (j, j^MASK), amplitudes packed (re,im).
// Side bit b(j) = lp ^ parity(j & PARJ) (validated convention, rel_err ~9e-7):
//   new[j]  = c*a[j]  + sgn*a[j2],  sgn = b ? s : -s ; new[j2] = c*a[j2] - sgn*a[j]
template<int MASK, unsigned PARJ>
__device__ __forceinline__ void rot_pk(ull (&st)[32], float c, float s, int lp)
{
    const float t = lp ? s : -s;
    const ull c2  = pk2(c, c);
    const ull t2  = pk2(t, t);
    const ull nt2 = pk2(-t, -t);
    constexpr int LOW = MASK & (-MASK);
#pragma unroll
    for (int j = 0; j < 32; ++j) {
        if ((j & LOW) == 0) {
            const int j2 = j ^ MASK;
            const ull sp = par((unsigned)j & PARJ) ? nt2 : t2;   // sgn
            const ull sn = par((unsigned)j & PARJ) ? t2  : nt2;  // -sgn
            ull a0 = st[j], a1 = st[j2];
            st[j]  = fma2(c2, a0, mul2(sp, a1));
            st[j2] = fma2(c2, a1, mul2(sn, a0));
        }
    }
}

__global__ void __launch_bounds__(WPB * 32, 4)
vqc_kernel(const float* __restrict__ x, const float* __restrict__ W,
           const float* __restrict__ b, const float* __restrict__ theta,
           float* __restrict__ out, int batch)
{
    // Wp[p][d] = packed (W[d][2p], W[d][2p+1])  — adjacent floats in W
    __shared__ __align__(16) ull Wp[5][DIN];
    __shared__ __align__(16) ull tb[WPB][32 * 32];   // XOR-swizzled transpose buffer
    __shared__ float bsh[NQ];
    __shared__ float thh[NQ];                // 0.5*theta[0][q][0]
    __shared__ float cz1[NQ], sz1[NQ];       // layer-1 RZ half cos/sin
    __shared__ float cy2[NQ], sy2[NQ];       // layer-2 RY half cos/sin

    const int tid = threadIdx.x;

    {
        const ull* Wsrc = reinterpret_cast<const ull*>(W);  // pairs (q=2p, 2p+1)
        for (int m = tid; m < 5 * DIN; m += blockDim.x) {
            int d = m / 5, p = m - d * 5;
            Wp[p][d] = Wsrc[m];
        }
    }
    if (tid < NQ) {
        bsh[tid] = b[tid];
        thh[tid] = 0.5f * theta[tid * 2 + 0];
        float hz1 = 0.5f * theta[tid * 2 + 1];
        cz1[tid] = cosf(hz1); sz1[tid] = sinf(hz1);
        float hy2 = 0.5f * theta[(NQ + tid) * 2 + 0];
        cy2[tid] = cosf(hy2); sy2[tid] = sinf(hy2);
    }
    __syncthreads();

    const int warp = blockIdx.x * WPB + (tid >> 5);
    if (warp >= batch) return;
    const int lane = tid & 31;
    ull* buf = tb[tid >> 5];

    // ---------------- Dense encoder (packed: 2 qubits per accumulator) ------
    float ang[NQ];
    {
        const float4* xr = reinterpret_cast<const float4*>(x + (size_t)warp * DIN);
        float4 xv0 = xr[lane];        // d = 4*lane .. 4*lane+3
        float4 xv1 = xr[lane + 32];   // d = 128 + 4*lane ..
        ull xp[8];
        xp[0] = pk2(xv0.x, xv0.x); xp[1] = pk2(xv0.y, xv0.y);
        xp[2] = pk2(xv0.z, xv0.z); xp[3] = pk2(xv0.w, xv0.w);
        xp[4] = pk2(xv1.x, xv1.x); xp[5] = pk2(xv1.y, xv1.y);
        xp[6] = pk2(xv1.z, xv1.z); xp[7] = pk2(xv1.w, xv1.w);
#pragma unroll
        for (int p = 0; p < 5; ++p) {
            const ulonglong2* wr = reinterpret_cast<const ulonglong2*>(&Wp[p][0]);
            ulonglong2 wa = wr[2 * lane];        // d = 4lane, 4lane+1
            ulonglong2 wb = wr[2 * lane + 1];    // d = 4lane+2, 4lane+3
            ulonglong2 wc = wr[2 * lane + 64];   // d = 128+4lane, +1
            ulonglong2 wd = wr[2 * lane + 65];   // d = 128+4lane+2, +3
            ull acc2 = mul2(xp[0], wa.x);
            acc2 = fma2(xp[1], wa.y, acc2);
            acc2 = fma2(xp[2], wb.x, acc2);
            acc2 = fma2(xp[3], wb.y, acc2);
            acc2 = fma2(xp[4], wc.x, acc2);
            acc2 = fma2(xp[5], wc.y, acc2);
            acc2 = fma2(xp[6], wd.x, acc2);
            acc2 = fma2(xp[7], wd.y, acc2);
#pragma unroll
            for (int o = 16; o; o >>= 1)
                acc2 = add2(acc2, __shfl_xor_sync(FULLM, acc2, o));
            float a0, a1; upk2(a0, a1, acc2);
            ang[2 * p]     = a0 + bsh[2 * p];
            ang[2 * p + 1] = a1 + bsh[2 * p + 1];
        }
    }

    // ---------------- Initial product state (enc RY + L1 RY + L1 RZ) --------
    // Layout: reg bits 0..4 = phys qubits 0..4, lane bits 0..4 = phys 5..9.
    float lfr = 1.f, lfi = 0.f;
#pragma unroll
    for (int qb = 0; qb < 5; ++qb) {
        const int q = 5 + qb;
        float h = 0.5f * ang[q] + thh[q];
        float sn, c;
        __sincosf(h, &sn, &c);
        float cz = cz1[q], sz = sz1[q];
        int bit = (lane >> qb) & 1;
        float amp = bit ? sn : c;
        float ph  = bit ? sz : -sz;
        float vr = amp * cz;
        float vi = amp * ph;
        float nr = lfr * vr - lfi * vi;
        float ni = lfr * vi + lfi * vr;
        lfr = nr; lfi = ni;
    }
    float u0r[5], u0i[5], u1r[5], u1i[5];
#pragma unroll
    for (int q = 0; q < 5; ++q) {
        float h = 0.5f * ang[q] + thh[q];
        float sn, c;
        __sincosf(h, &sn, &c);
        float cz = cz1[q], sz = sz1[q];
        u0r[q] = c * cz;  u0i[q] = -c * sz;
        u1r[q] = sn * cz; u1i[q] = sn * sz;
    }
    float sr[32], si[32];
    sr[0] = lfr; si[0] = lfi;
#pragma unroll
    for (int q = 0; q < 5; ++q) {
        const int n = 1 << q;
#pragma unroll
        for (int j = n - 1; j >= 0; --j) {
            float xr0 = sr[j], xi0 = si[j];
            sr[j + n] = xr0 * u1r[q] - xi0 * u1i[q];
            si[j + n] = xr0 * u1i[q] + xi0 * u1r[q];
            sr[j]     = xr0 * u0r[q] - xi0 * u0i[q];
            si[j]     = xr0 * u0i[q] + xi0 * u0r[q];
        }
    }
    // pack state: st[j] = (re, im)
    ull st[32];
#pragma unroll
    for (int j = 0; j < 32; ++j) st[j] = pk2(sr[j], si[j]);

    // ---------------- CNOT chain #1 = relabeling (A = L). Layer-2 RY on
    // logical q pairs PHYSICAL bits {q, q+1} ({9} for q=9); side bit
    // b = parity(phys bits 0..q). Rotations commute -> free ordering.

    // q = 0..3 : reg-only pairs
    rot_pk<0x03, 0x01>(st, cy2[0], sy2[0], 0);
    rot_pk<0x06, 0x03>(st, cy2[1], sy2[1], 0);
    rot_pk<0x0C, 0x07>(st, cy2[2], sy2[2], 0);
    rot_pk<0x18, 0x0F>(st, cy2[3], sy2[3], 0);

    // q = 4 : pairs phys{4,5} = reg bit 4 & lane bit 0
    {
        const float c = cy2[4], s = sy2[4];
        const ull c2 = pk2(c, c);
#pragma unroll
        for (int j = 0; j < 16; ++j) {
            const int j2 = j | 16;
            ull o0 = __shfl_xor_sync(FULLM, st[j2], 1);
            ull o1 = __shfl_xor_sync(FULLM, st[j],  1);
            const float sj = par((unsigned)j) ? s : -s;
            const ull sp = pk2(sj, sj), sn = pk2(-sj, -sj);
            st[j]  = fma2(c2, st[j],  mul2(sp, o0));
            st[j2] = fma2(c2, st[j2], mul2(sn, o1));
        }
    }

    // ---------------- Transpose reg bits <-> lane bits (XOR-swizzled smem) --
    // New layout: reg bit m = phys 5+m, lane bit m = phys m.
    {
#pragma unroll
        for (int j = 0; j < 32; ++j) buf[lane * 32 + (j ^ lane)] = st[j];
        __syncwarp();
#pragma unroll
        for (int j = 0; j < 32; ++j) st[j] = buf[j * 32 + (lane ^ j)];
    }

    // q = 5..9 : reg-only. b = par(lane&31) ^ par(j & ((1<<(q-4))-1))
    {
        const int lp = __popc(lane & 0x1F) & 1;
        rot_pk<0x03, 0x01>(st, cy2[5], sy2[5], lp);
        rot_pk<0x06, 0x03>(st, cy2[6], sy2[6], lp);
        rot_pk<0x0C, 0x07>(st, cy2[7], sy2[7], lp);
        rot_pk<0x18, 0x0F>(st, cy2[8], sy2[8], lp);
        rot_pk<0x10, 0x1F>(st, cy2[9], sy2[9], lp);
    }

    // (Layer-2 RZ dropped: diagonal before a permutation + |.|^2.)
    // ---------------- CNOT chain #2 = relabeling (A = L^2) + measurement ----
    // Layout: lane bits = phys 0..4, reg bits = phys 5..9.
    const int p0 = lane & 1;
    const int p1 = (lane >> 1) & 1;
    const int p2 = __popc(lane & 0x05) & 1;
    const int pA = __popc(lane & 0x0A) & 1;   // rows {1,3}
    const int pB = __popc(lane & 0x15) & 1;   // rows {0,2,4}
    const int Llow  = p0 + p1 + p2 + pA + pB;             // t = 0..4
    const int LaneH = pA * 0x15 + pB * 0x0A;              // lane part of t = 5..9

    ull acc2 = 0;
#pragma unroll
    for (int j = 0; j < 32; ++j) {
        const int Jbits = (j & 1)
                        | (((j >> 1) & 1) << 1)
                        | (par((unsigned)j & 0x05u) << 2)
                        | (par((unsigned)j & 0x0Au) << 3)
                        | (par((unsigned)j & 0x15u) << 4);
        const int pn = Llow + __popc(Jbits ^ LaneH);
        const float w = 1.0f - 0.2f * (float)pn;
        acc2 = fma2(mul2(st[j], st[j]), pk2(w, w), acc2);
    }
    float ar, ai; upk2(ar, ai, acc2);
    float acc = ar + ai;
#pragma unroll
    for (int o = 16; o; o >>= 1) acc += __shfl_xor_sync(FULLM, acc, o);
    if (lane == 0) out[warp] = acc;
}

extern "C" void kernel_launch(void* const* d_in, const int* in_sizes, int n_in,
                              void* d_out, int out_size)
{
    const float* x  = nullptr;
    const float* W  = nullptr;
    const float* b  = nullptr;
    const float* th = nullptr;
    for (int i = 0; i < n_in; ++i) {
        int sz = in_sizes[i];
        if      (sz == 4096 * 256) x  = (const float*)d_in[i];
        else if (sz == 256 * 10)   W  = (const float*)d_in[i];
        else if (sz == 10)         b  = (const float*)d_in[i];
        else if (sz == 2 * 10 * 2) th = (const float*)d_in[i];
    }
    if (!x)  x  = (const float*)d_in[0];
    if (!W)  W  = (const float*)d_in[1];
    if (!b)  b  = (const float*)d_in[2];
    if (!th) th = (const float*)d_in[3];

    int batch = out_size;
    int blocks = (batch + WPB - 1) / WPB;
    vqc_kernel<<<blocks, WPB * 32>>>(x, W, b, th, (float*)d_out, batch);
}